// round 1
// baseline (speedup 1.0000x reference)
#include <cuda_runtime.h>
#include <cstdint>

#define B_BATCH 4
#define T_SEQ   2048
#define C_EMB   1024
#define H_HEADS 16
#define D_HEAD  64

// Scratch (device globals: allocation-free per harness rules)
__device__ float g_q [B_BATCH * H_HEADS * T_SEQ * D_HEAD];   // 32 MB
__device__ float g_k [B_BATCH * H_HEADS * T_SEQ * D_HEAD];   // 32 MB
__device__ float g_v [B_BATCH * H_HEADS * T_SEQ * D_HEAD];   // 32 MB
__device__ float g_ao[B_BATCH * T_SEQ * C_EMB];              // 32 MB, [B,T,C]

__device__ __forceinline__ float neg_inf() { return __int_as_float(0xff800000); }

// ---------------------------------------------------------------------------
// GEMM (NT): Y[m,n] = sum_k A[m,k] * W[n,k] + bias[n]
// MODE 0: A = x, scatter Y into g_q/g_k/g_v as [B,H,T,D]
// MODE 1: A = g_ao (A arg ignored), write Y row-major to Cout
// BM=BN=128, BK=16, 256 threads, 8x8 per thread.
// ---------------------------------------------------------------------------
template<int MODE>
__global__ __launch_bounds__(256)
void gemm_nt(const float* __restrict__ A, const float* __restrict__ W,
             const float* __restrict__ bias, float* __restrict__ Cout,
             int M, int N, int K)
{
    __shared__ float As[16][128];
    __shared__ float Bs[16][128];

    const float* Ap = (MODE == 1) ? (const float*)g_ao : A;

    const int tid  = threadIdx.x;
    const int bm   = blockIdx.y * 128;
    const int bn   = blockIdx.x * 128;
    const int rowb = (tid >> 4) * 8;
    const int colb = (tid & 15) * 8;
    const int lr   = tid >> 2;        // 0..63
    const int lc4  = (tid & 3) * 4;   // 0,4,8,12

    float acc[8][8];
    #pragma unroll
    for (int i = 0; i < 8; i++)
        #pragma unroll
        for (int j = 0; j < 8; j++) acc[i][j] = 0.f;

    for (int kt = 0; kt < K; kt += 16) {
        #pragma unroll
        for (int half = 0; half < 2; half++) {
            int r = lr + half * 64;
            float4 a = *(const float4*)(Ap + (size_t)(bm + r) * K + kt + lc4);
            As[lc4 + 0][r] = a.x; As[lc4 + 1][r] = a.y;
            As[lc4 + 2][r] = a.z; As[lc4 + 3][r] = a.w;
            float4 b = *(const float4*)(W + (size_t)(bn + r) * K + kt + lc4);
            Bs[lc4 + 0][r] = b.x; Bs[lc4 + 1][r] = b.y;
            Bs[lc4 + 2][r] = b.z; Bs[lc4 + 3][r] = b.w;
        }
        __syncthreads();

        #pragma unroll
        for (int k = 0; k < 16; k++) {
            float4 a0 = *(const float4*)&As[k][rowb];
            float4 a1 = *(const float4*)&As[k][rowb + 4];
            float4 b0 = *(const float4*)&Bs[k][colb];
            float4 b1 = *(const float4*)&Bs[k][colb + 4];
            float av[8] = {a0.x, a0.y, a0.z, a0.w, a1.x, a1.y, a1.z, a1.w};
            float bv[8] = {b0.x, b0.y, b0.z, b0.w, b1.x, b1.y, b1.z, b1.w};
            #pragma unroll
            for (int i = 0; i < 8; i++)
                #pragma unroll
                for (int j = 0; j < 8; j++)
                    acc[i][j] = fmaf(av[i], bv[j], acc[i][j]);
        }
        __syncthreads();
    }

    if (MODE == 0) {
        // scatter into q/k/v [B,H,T,D]
        #pragma unroll
        for (int i = 0; i < 8; i++) {
            int m  = bm + rowb + i;
            int bb = m >> 11;          // /T_SEQ
            int t  = m & 2047;
            #pragma unroll
            for (int j = 0; j < 8; j++) {
                int n = bn + colb + j;
                float v = acc[i][j] + bias[n];
                int which = n >> 10;           // 0=q 1=k 2=v
                int hh = (n >> 6) & 15;
                int dd = n & 63;
                float* dst = (which == 0) ? g_q : (which == 1) ? g_k : g_v;
                dst[(((size_t)bb * H_HEADS + hh) * T_SEQ + t) * D_HEAD + dd] = v;
            }
        }
    } else {
        #pragma unroll
        for (int i = 0; i < 8; i++) {
            int m = bm + rowb + i;
            #pragma unroll
            for (int j4 = 0; j4 < 2; j4++) {
                int n0 = bn + colb + j4 * 4;
                float4 o;
                o.x = acc[i][j4 * 4 + 0] + bias[n0 + 0];
                o.y = acc[i][j4 * 4 + 1] + bias[n0 + 1];
                o.z = acc[i][j4 * 4 + 2] + bias[n0 + 2];
                o.w = acc[i][j4 * 4 + 3] + bias[n0 + 3];
                *(float4*)(Cout + (size_t)m * N + n0) = o;
            }
        }
    }
}

// ---------------------------------------------------------------------------
// Flash attention: grid (T/64, B*H). 256 threads as 16x16; each thread owns a
// 4x4 S-subtile and a 4x4 O-subtile. K transposed in smem; online softmax.
// ---------------------------------------------------------------------------
#define ATTN_SMEM_FLOATS (64*64 + 64*68 + 64*64 + 64*64)   // Qs, Kts, Vs, Ps
#define ATTN_SMEM_BYTES  (ATTN_SMEM_FLOATS * 4)

__global__ __launch_bounds__(256)
void attn_fused(const int* __restrict__ mask)
{
    extern __shared__ float sm[];
    float* Qs  = sm;                  // [64][64]  row=query, col=d
    float* Kts = sm + 64 * 64;        // [64][68]  row=d, col=key (padded)
    float* Vs  = Kts + 64 * 68;       // [64][64]  row=key, col=d
    float* Ps  = Vs + 64 * 64;        // [64][64]  row=query, col=key
    __shared__ int msk[64];

    const int tid = threadIdx.x;
    const int tx = tid & 15, ty = tid >> 4;
    const int bh = blockIdx.y;
    const int b = bh >> 4, h = bh & 15;
    const int q0 = blockIdx.x * 64;

    const float* Qg = g_q + (size_t)bh * T_SEQ * D_HEAD + (size_t)q0 * D_HEAD;
    const float* Kg = g_k + (size_t)bh * T_SEQ * D_HEAD;
    const float* Vg = g_v + (size_t)bh * T_SEQ * D_HEAD;

    // load Q tile (64x64), float4
    #pragma unroll
    for (int it = 0; it < 4; it++) {
        int i = tid + it * 256;           // float4 index, 0..1023
        int r = i >> 4, c4 = (i & 15) * 4;
        *(float4*)&Qs[r * 64 + c4] = *(const float4*)(Qg + (size_t)r * 64 + c4);
    }

    float m_i[4], l_i[4], O[4][4];
    #pragma unroll
    for (int i = 0; i < 4; i++) {
        m_i[i] = neg_inf(); l_i[i] = 0.f;
        #pragma unroll
        for (int j = 0; j < 4; j++) O[i][j] = 0.f;
    }

    for (int kt = 0; kt < T_SEQ; kt += 64) {
        __syncthreads();   // prior PV done (and covers the Q load on iter 0)
        #pragma unroll
        for (int it = 0; it < 4; it++) {
            int i = tid + it * 256;
            int r = i >> 4, c4 = (i & 15) * 4;
            float4 kv = *(const float4*)(Kg + (size_t)(kt + r) * 64 + c4);
            Kts[(c4 + 0) * 68 + r] = kv.x;
            Kts[(c4 + 1) * 68 + r] = kv.y;
            Kts[(c4 + 2) * 68 + r] = kv.z;
            Kts[(c4 + 3) * 68 + r] = kv.w;
            *(float4*)&Vs[r * 64 + c4] = *(const float4*)(Vg + (size_t)(kt + r) * 64 + c4);
        }
        if (tid < 64) msk[tid] = mask[b * T_SEQ + kt + tid];
        __syncthreads();

        // S = Q K^T  (4x4 per thread)
        float s[4][4];
        #pragma unroll
        for (int i = 0; i < 4; i++)
            #pragma unroll
            for (int j = 0; j < 4; j++) s[i][j] = 0.f;

        #pragma unroll
        for (int d4 = 0; d4 < 16; d4++) {
            float qv[4][4], kv[4][4];
            #pragma unroll
            for (int i = 0; i < 4; i++) {
                float4 t = *(const float4*)&Qs[(ty * 4 + i) * 64 + d4 * 4];
                qv[i][0] = t.x; qv[i][1] = t.y; qv[i][2] = t.z; qv[i][3] = t.w;
            }
            #pragma unroll
            for (int dd = 0; dd < 4; dd++) {
                float4 t = *(const float4*)&Kts[(d4 * 4 + dd) * 68 + tx * 4];
                kv[dd][0] = t.x; kv[dd][1] = t.y; kv[dd][2] = t.z; kv[dd][3] = t.w;
            }
            #pragma unroll
            for (int i = 0; i < 4; i++)
                #pragma unroll
                for (int j = 0; j < 4; j++)
                    #pragma unroll
                    for (int dd = 0; dd < 4; dd++)
                        s[i][j] = fmaf(qv[i][dd], kv[dd][j], s[i][j]);
        }

        // mask + scale (1/sqrt(64) = 0.125)
        #pragma unroll
        for (int j = 0; j < 4; j++) {
            bool valid = msk[tx * 4 + j] != 0;
            #pragma unroll
            for (int i = 0; i < 4; i++)
                s[i][j] = valid ? s[i][j] * 0.125f : neg_inf();
        }

        // online softmax update per row
        float alpha[4];
        #pragma unroll
        for (int i = 0; i < 4; i++) {
            float mloc = fmaxf(fmaxf(s[i][0], s[i][1]), fmaxf(s[i][2], s[i][3]));
            #pragma unroll
            for (int off = 8; off > 0; off >>= 1)
                mloc = fmaxf(mloc, __shfl_xor_sync(0xffffffffu, mloc, off, 16));
            float mn = fmaxf(m_i[i], mloc);
            float mu = (mn == neg_inf()) ? 0.f : mn;   // guard fully-masked rows
            alpha[i] = __expf(m_i[i] - mu);            // -inf -> 0, safe
            float p0 = __expf(s[i][0] - mu);
            float p1 = __expf(s[i][1] - mu);
            float p2 = __expf(s[i][2] - mu);
            float p3 = __expf(s[i][3] - mu);
            float rs = (p0 + p1) + (p2 + p3);
            #pragma unroll
            for (int off = 8; off > 0; off >>= 1)
                rs += __shfl_xor_sync(0xffffffffu, rs, off, 16);
            l_i[i] = l_i[i] * alpha[i] + rs;
            m_i[i] = mn;
            *(float4*)&Ps[(ty * 4 + i) * 64 + tx * 4] = make_float4(p0, p1, p2, p3);
            #pragma unroll
            for (int j = 0; j < 4; j++) O[i][j] *= alpha[i];
        }
        __syncthreads();

        // O += P V
        #pragma unroll
        for (int j4 = 0; j4 < 16; j4++) {
            float pv[4][4], vv[4][4];
            #pragma unroll
            for (int i = 0; i < 4; i++) {
                float4 t = *(const float4*)&Ps[(ty * 4 + i) * 64 + j4 * 4];
                pv[i][0] = t.x; pv[i][1] = t.y; pv[i][2] = t.z; pv[i][3] = t.w;
            }
            #pragma unroll
            for (int dd = 0; dd < 4; dd++) {
                float4 t = *(const float4*)&Vs[(j4 * 4 + dd) * 64 + tx * 4];
                vv[dd][0] = t.x; vv[dd][1] = t.y; vv[dd][2] = t.z; vv[dd][3] = t.w;
            }
            #pragma unroll
            for (int i = 0; i < 4; i++)
                #pragma unroll
                for (int j = 0; j < 4; j++)
                    #pragma unroll
                    for (int dd = 0; dd < 4; dd++)
                        O[i][j] = fmaf(pv[i][dd], vv[dd][j], O[i][j]);
        }
    }

    // epilogue: normalize + write to g_ao as [B,T,C]
    float* outp = g_ao + ((size_t)(b * T_SEQ + q0)) * C_EMB + h * D_HEAD;
    #pragma unroll
    for (int i = 0; i < 4; i++) {
        float inv = 1.f / l_i[i];
        float4 o = make_float4(O[i][0] * inv, O[i][1] * inv,
                               O[i][2] * inv, O[i][3] * inv);
        *(float4*)(outp + (size_t)(ty * 4 + i) * C_EMB + tx * 4) = o;
    }
}

// ---------------------------------------------------------------------------
extern "C" void kernel_launch(void* const* d_in, const int* in_sizes, int n_in,
                              void* d_out, int out_size)
{
    const float* x      = (const float*)d_in[0];
    const int*   mask   = (const int*)  d_in[1];
    const float* qkv_w  = (const float*)d_in[2];
    const float* qkv_b  = (const float*)d_in[3];
    const float* out_w  = (const float*)d_in[4];
    const float* out_b  = (const float*)d_in[5];
    float*       out    = (float*)d_out;

    const int M = B_BATCH * T_SEQ;   // 8192

    // 1) QKV projection, scatter into [B,H,T,D]
    gemm_nt<0><<<dim3(3 * C_EMB / 128, M / 128), 256>>>(
        x, qkv_w, qkv_b, nullptr, M, 3 * C_EMB, C_EMB);

    // 2) fused masked attention -> g_ao [B,T,C]
    cudaFuncSetAttribute(attn_fused, cudaFuncAttributeMaxDynamicSharedMemorySize,
                         ATTN_SMEM_BYTES);
    attn_fused<<<dim3(T_SEQ / 64, B_BATCH * H_HEADS), 256, ATTN_SMEM_BYTES>>>(mask);

    // 3) output projection -> d_out
    gemm_nt<1><<<dim3(C_EMB / 128, M / 128), 256>>>(
        nullptr, out_w, out_b, out, M, C_EMB, C_EMB);
}

// round 2
// speedup vs baseline: 1.0003x; 1.0003x over previous
#include <cuda_runtime.h>
#include <cstdint>

#define B_BATCH 4
#define T_SEQ   2048
#define C_EMB   1024
#define H_HEADS 16
#define D_HEAD  64

// Scratch (device globals: allocation-free per harness rules)
__device__ float g_q [B_BATCH * H_HEADS * T_SEQ * D_HEAD];   // 32 MB
__device__ float g_k [B_BATCH * H_HEADS * T_SEQ * D_HEAD];   // 32 MB
__device__ float g_v [B_BATCH * H_HEADS * T_SEQ * D_HEAD];   // 32 MB
__device__ float g_ao[B_BATCH * T_SEQ * C_EMB];              // 32 MB, [B,T,C]

__device__ __forceinline__ float neg_inf() { return __int_as_float(0xff800000); }

// ---------------------------------------------------------------------------
// GEMM (NT): Y[m,n] = sum_k A[m,k] * W[n,k] + bias[n]
// MODE 0: A = x, scatter Y into g_q/g_k/g_v as [B,H,T,D]
// MODE 1: A = g_ao (A arg ignored), write Y row-major to Cout
// BM=BN=128, BK=16, 256 threads, 8x8 per thread.
// ---------------------------------------------------------------------------
template<int MODE>
__global__ __launch_bounds__(256)
void gemm_nt(const float* __restrict__ A, const float* __restrict__ W,
             const float* __restrict__ bias, float* __restrict__ Cout,
             int M, int N, int K)
{
    __shared__ float As[16][128];
    __shared__ float Bs[16][128];

    const float* Ap = (MODE == 1) ? (const float*)g_ao : A;

    const int tid  = threadIdx.x;
    const int bm   = blockIdx.y * 128;
    const int bn   = blockIdx.x * 128;
    const int rowb = (tid >> 4) * 8;
    const int colb = (tid & 15) * 8;
    const int lr   = tid >> 2;        // 0..63
    const int lc4  = (tid & 3) * 4;   // 0,4,8,12

    float acc[8][8];
    #pragma unroll
    for (int i = 0; i < 8; i++)
        #pragma unroll
        for (int j = 0; j < 8; j++) acc[i][j] = 0.f;

    for (int kt = 0; kt < K; kt += 16) {
        #pragma unroll
        for (int half = 0; half < 2; half++) {
            int r = lr + half * 64;
            float4 a = *(const float4*)(Ap + (size_t)(bm + r) * K + kt + lc4);
            As[lc4 + 0][r] = a.x; As[lc4 + 1][r] = a.y;
            As[lc4 + 2][r] = a.z; As[lc4 + 3][r] = a.w;
            float4 b = *(const float4*)(W + (size_t)(bn + r) * K + kt + lc4);
            Bs[lc4 + 0][r] = b.x; Bs[lc4 + 1][r] = b.y;
            Bs[lc4 + 2][r] = b.z; Bs[lc4 + 3][r] = b.w;
        }
        __syncthreads();

        #pragma unroll
        for (int k = 0; k < 16; k++) {
            float4 a0 = *(const float4*)&As[k][rowb];
            float4 a1 = *(const float4*)&As[k][rowb + 4];
            float4 b0 = *(const float4*)&Bs[k][colb];
            float4 b1 = *(const float4*)&Bs[k][colb + 4];
            float av[8] = {a0.x, a0.y, a0.z, a0.w, a1.x, a1.y, a1.z, a1.w};
            float bv[8] = {b0.x, b0.y, b0.z, b0.w, b1.x, b1.y, b1.z, b1.w};
            #pragma unroll
            for (int i = 0; i < 8; i++)
                #pragma unroll
                for (int j = 0; j < 8; j++)
                    acc[i][j] = fmaf(av[i], bv[j], acc[i][j]);
        }
        __syncthreads();
    }

    if (MODE == 0) {
        // scatter into q/k/v [B,H,T,D]
        #pragma unroll
        for (int i = 0; i < 8; i++) {
            int m  = bm + rowb + i;
            int bb = m >> 11;          // /T_SEQ
            int t  = m & 2047;
            #pragma unroll
            for (int j = 0; j < 8; j++) {
                int n = bn + colb + j;
                float v = acc[i][j] + bias[n];
                int which = n >> 10;           // 0=q 1=k 2=v
                int hh = (n >> 6) & 15;
                int dd = n & 63;
                float* dst = (which == 0) ? g_q : (which == 1) ? g_k : g_v;
                dst[(((size_t)bb * H_HEADS + hh) * T_SEQ + t) * D_HEAD + dd] = v;
            }
        }
    } else {
        #pragma unroll
        for (int i = 0; i < 8; i++) {
            int m = bm + rowb + i;
            #pragma unroll
            for (int j4 = 0; j4 < 2; j4++) {
                int n0 = bn + colb + j4 * 4;
                float4 o;
                o.x = acc[i][j4 * 4 + 0] + bias[n0 + 0];
                o.y = acc[i][j4 * 4 + 1] + bias[n0 + 1];
                o.z = acc[i][j4 * 4 + 2] + bias[n0 + 2];
                o.w = acc[i][j4 * 4 + 3] + bias[n0 + 3];
                *(float4*)(Cout + (size_t)m * N + n0) = o;
            }
        }
    }
}

// ---------------------------------------------------------------------------
// Flash attention: grid (T/64, B*H). 256 threads as 16x16; each thread owns a
// 4x4 S-subtile and a 4x4 O-subtile. K transposed in smem; online softmax.
// ---------------------------------------------------------------------------
#define ATTN_SMEM_FLOATS (64*64 + 64*68 + 64*64 + 64*64)   // Qs, Kts, Vs, Ps
#define ATTN_SMEM_BYTES  (ATTN_SMEM_FLOATS * 4)

__global__ __launch_bounds__(256)
void attn_fused(const int* __restrict__ mask)
{
    extern __shared__ float sm[];
    float* Qs  = sm;                  // [64][64]  row=query, col=d
    float* Kts = sm + 64 * 64;        // [64][68]  row=d, col=key (padded)
    float* Vs  = Kts + 64 * 68;       // [64][64]  row=key, col=d
    float* Ps  = Vs + 64 * 64;        // [64][64]  row=query, col=key
    __shared__ int msk[64];

    const int tid = threadIdx.x;
    const int tx = tid & 15, ty = tid >> 4;
    const int bh = blockIdx.y;
    const int b = bh >> 4, h = bh & 15;
    const int q0 = blockIdx.x * 64;

    const float* Qg = g_q + (size_t)bh * T_SEQ * D_HEAD + (size_t)q0 * D_HEAD;
    const float* Kg = g_k + (size_t)bh * T_SEQ * D_HEAD;
    const float* Vg = g_v + (size_t)bh * T_SEQ * D_HEAD;

    // load Q tile (64x64), float4
    #pragma unroll
    for (int it = 0; it < 4; it++) {
        int i = tid + it * 256;           // float4 index, 0..1023
        int r = i >> 4, c4 = (i & 15) * 4;
        *(float4*)&Qs[r * 64 + c4] = *(const float4*)(Qg + (size_t)r * 64 + c4);
    }

    float m_i[4], l_i[4], O[4][4];
    #pragma unroll
    for (int i = 0; i < 4; i++) {
        m_i[i] = neg_inf(); l_i[i] = 0.f;
        #pragma unroll
        for (int j = 0; j < 4; j++) O[i][j] = 0.f;
    }

    for (int kt = 0; kt < T_SEQ; kt += 64) {
        __syncthreads();   // prior PV done (and covers the Q load on iter 0)
        #pragma unroll
        for (int it = 0; it < 4; it++) {
            int i = tid + it * 256;
            int r = i >> 4, c4 = (i & 15) * 4;
            float4 kv = *(const float4*)(Kg + (size_t)(kt + r) * 64 + c4);
            Kts[(c4 + 0) * 68 + r] = kv.x;
            Kts[(c4 + 1) * 68 + r] = kv.y;
            Kts[(c4 + 2) * 68 + r] = kv.z;
            Kts[(c4 + 3) * 68 + r] = kv.w;
            *(float4*)&Vs[r * 64 + c4] = *(const float4*)(Vg + (size_t)(kt + r) * 64 + c4);
        }
        if (tid < 64) msk[tid] = mask[b * T_SEQ + kt + tid];
        __syncthreads();

        // S = Q K^T  (4x4 per thread)
        float s[4][4];
        #pragma unroll
        for (int i = 0; i < 4; i++)
            #pragma unroll
            for (int j = 0; j < 4; j++) s[i][j] = 0.f;

        #pragma unroll
        for (int d4 = 0; d4 < 16; d4++) {
            float qv[4][4], kv[4][4];
            #pragma unroll
            for (int i = 0; i < 4; i++) {
                float4 t = *(const float4*)&Qs[(ty * 4 + i) * 64 + d4 * 4];
                qv[i][0] = t.x; qv[i][1] = t.y; qv[i][2] = t.z; qv[i][3] = t.w;
            }
            #pragma unroll
            for (int dd = 0; dd < 4; dd++) {
                float4 t = *(const float4*)&Kts[(d4 * 4 + dd) * 68 + tx * 4];
                kv[dd][0] = t.x; kv[dd][1] = t.y; kv[dd][2] = t.z; kv[dd][3] = t.w;
            }
            #pragma unroll
            for (int i = 0; i < 4; i++)
                #pragma unroll
                for (int j = 0; j < 4; j++)
                    #pragma unroll
                    for (int dd = 0; dd < 4; dd++)
                        s[i][j] = fmaf(qv[i][dd], kv[dd][j], s[i][j]);
        }

        // mask + scale (1/sqrt(64) = 0.125)
        #pragma unroll
        for (int j = 0; j < 4; j++) {
            bool valid = msk[tx * 4 + j] != 0;
            #pragma unroll
            for (int i = 0; i < 4; i++)
                s[i][j] = valid ? s[i][j] * 0.125f : neg_inf();
        }

        // online softmax update per row
        float alpha[4];
        #pragma unroll
        for (int i = 0; i < 4; i++) {
            float mloc = fmaxf(fmaxf(s[i][0], s[i][1]), fmaxf(s[i][2], s[i][3]));
            #pragma unroll
            for (int off = 8; off > 0; off >>= 1)
                mloc = fmaxf(mloc, __shfl_xor_sync(0xffffffffu, mloc, off, 16));
            float mn = fmaxf(m_i[i], mloc);
            float mu = (mn == neg_inf()) ? 0.f : mn;   // guard fully-masked rows
            alpha[i] = __expf(m_i[i] - mu);            // -inf -> 0, safe
            float p0 = __expf(s[i][0] - mu);
            float p1 = __expf(s[i][1] - mu);
            float p2 = __expf(s[i][2] - mu);
            float p3 = __expf(s[i][3] - mu);
            float rs = (p0 + p1) + (p2 + p3);
            #pragma unroll
            for (int off = 8; off > 0; off >>= 1)
                rs += __shfl_xor_sync(0xffffffffu, rs, off, 16);
            l_i[i] = l_i[i] * alpha[i] + rs;
            m_i[i] = mn;
            *(float4*)&Ps[(ty * 4 + i) * 64 + tx * 4] = make_float4(p0, p1, p2, p3);
            #pragma unroll
            for (int j = 0; j < 4; j++) O[i][j] *= alpha[i];
        }
        __syncthreads();

        // O += P V
        #pragma unroll
        for (int j4 = 0; j4 < 16; j4++) {
            float pv[4][4], vv[4][4];
            #pragma unroll
            for (int i = 0; i < 4; i++) {
                float4 t = *(const float4*)&Ps[(ty * 4 + i) * 64 + j4 * 4];
                pv[i][0] = t.x; pv[i][1] = t.y; pv[i][2] = t.z; pv[i][3] = t.w;
            }
            #pragma unroll
            for (int dd = 0; dd < 4; dd++) {
                float4 t = *(const float4*)&Vs[(j4 * 4 + dd) * 64 + tx * 4];
                vv[dd][0] = t.x; vv[dd][1] = t.y; vv[dd][2] = t.z; vv[dd][3] = t.w;
            }
            #pragma unroll
            for (int i = 0; i < 4; i++)
                #pragma unroll
                for (int j = 0; j < 4; j++)
                    #pragma unroll
                    for (int dd = 0; dd < 4; dd++)
                        O[i][j] = fmaf(pv[i][dd], vv[dd][j], O[i][j]);
        }
    }

    // epilogue: normalize + write to g_ao as [B,T,C]
    float* outp = g_ao + ((size_t)(b * T_SEQ + q0)) * C_EMB + h * D_HEAD;
    #pragma unroll
    for (int i = 0; i < 4; i++) {
        float inv = 1.f / l_i[i];
        float4 o = make_float4(O[i][0] * inv, O[i][1] * inv,
                               O[i][2] * inv, O[i][3] * inv);
        *(float4*)(outp + (size_t)(ty * 4 + i) * C_EMB + tx * 4) = o;
    }
}

// ---------------------------------------------------------------------------
extern "C" void kernel_launch(void* const* d_in, const int* in_sizes, int n_in,
                              void* d_out, int out_size)
{
    const float* x      = (const float*)d_in[0];
    const int*   mask   = (const int*)  d_in[1];
    const float* qkv_w  = (const float*)d_in[2];
    const float* qkv_b  = (const float*)d_in[3];
    const float* out_w  = (const float*)d_in[4];
    const float* out_b  = (const float*)d_in[5];
    float*       out    = (float*)d_out;

    const int M = B_BATCH * T_SEQ;   // 8192

    // 1) QKV projection, scatter into [B,H,T,D]
    gemm_nt<0><<<dim3(3 * C_EMB / 128, M / 128), 256>>>(
        x, qkv_w, qkv_b, nullptr, M, 3 * C_EMB, C_EMB);

    // 2) fused masked attention -> g_ao [B,T,C]
    cudaFuncSetAttribute(attn_fused, cudaFuncAttributeMaxDynamicSharedMemorySize,
                         ATTN_SMEM_BYTES);
    attn_fused<<<dim3(T_SEQ / 64, B_BATCH * H_HEADS), 256, ATTN_SMEM_BYTES>>>(mask);

    // 3) output projection -> d_out
    gemm_nt<1><<<dim3(C_EMB / 128, M / 128), 256>>>(
        nullptr, out_w, out_b, out, M, C_EMB, C_EMB);
}